// round 15
// baseline (speedup 1.0000x reference)
#include <cuda_runtime.h>
#include <cuda_fp16.h>

#define NU 200000
#define NI 100000
#define NN (NU + NI)          // nodes per pass
#define NN2 (2 * NN)
#define EMAX_TOT 2500000
#define SCAN_ITEMS 2048
#define MAX_NB 512
#define NBUCK 256             // degree buckets per pass

// e-buffers in RANK space: row = 128B fp16 = 8 uint4. e[0..3]; e4 fused out.
__device__ __align__(256) uint4 g_e[4][NN2 * 8];
__device__ int    g_cnt[NN2];
__device__ int    g_cur[NN2];
__device__ int    g_soff[NN2 + 2];   // pos: [0..NN], neg: [NN+1..2NN+1]
__device__ int    g_bsumP[MAX_NB];
__device__ int    g_bsumN[MAX_NB];
__device__ int    g_hist[2 * NBUCK];
__device__ int    g_hoff[2 * NBUCK];
__device__ int    g_perm[NN2];
__device__ int    g_rank[NN2];
__device__ float2 g_pl[2 * EMAX_TOT];   // {neighbor RANK (bits), norm}

// ---- packed f32x2 helpers (SASS FFMA2 path, PTX-only) ----
__device__ __forceinline__ unsigned long long packf2(float x, float y) {
    unsigned long long r;
    asm("mov.b64 %0, {%1, %2};" : "=l"(r) : "f"(x), "f"(y));
    return r;
}
__device__ __forceinline__ float2 unpackf2(unsigned long long v) {
    float2 f;
    asm("mov.b64 {%0, %1}, %2;" : "=f"(f.x), "=f"(f.y) : "l"(v));
    return f;
}
__device__ __forceinline__ void ffma2(unsigned long long& acc,
                                      unsigned long long a, unsigned long long b) {
    asm("fma.rn.f32x2 %0, %1, %2, %0;" : "+l"(acc) : "l"(a), "l"(b));
}
__device__ __forceinline__ void fadd2(unsigned long long& acc, unsigned long long a) {
    asm("add.rn.f32x2 %0, %1, %0;" : "+l"(acc) : "l"(a));
}
// acc[i] += w.half2[i] * nn  (nn = packed {n,n})
__device__ __forceinline__ void fma8p(unsigned long long acc[4], uint4 w,
                                      unsigned long long nn) {
    __half2* hp = (__half2*)&w;
#pragma unroll
    for (int i = 0; i < 4; i++) {
        float2 f = __half22float2(hp[i]);
        ffma2(acc[i], packf2(f.x, f.y), nn);
    }
}
__device__ __forceinline__ void acc_init(unsigned long long acc[4], uint4 v) {
    __half2* hp = (__half2*)&v;
#pragma unroll
    for (int i = 0; i < 4; i++) {
        float2 f = __half22float2(hp[i]);
        acc[i] = packf2(f.x, f.y);
    }
}
__device__ __forceinline__ uint4 acc_pack16(const unsigned long long acc[4]) {
    uint4 o;
    __half2* hp = (__half2*)&o;
#pragma unroll
    for (int i = 0; i < 4; i++) {
        float2 f = unpackf2(acc[i]);
        hp[i] = __floats2half2_rn(f.x, f.y);
    }
    return o;
}

__device__ __forceinline__ uint4 pack8(const float4& a, const float4& b) {
    __half2 h0 = __floats2half2_rn(a.x, a.y);
    __half2 h1 = __floats2half2_rn(a.z, a.w);
    __half2 h2 = __floats2half2_rn(b.x, b.y);
    __half2 h3 = __floats2half2_rn(b.z, b.w);
    uint4 r;
    r.x = *(unsigned*)&h0; r.y = *(unsigned*)&h1;
    r.z = *(unsigned*)&h2; r.w = *(unsigned*)&h3;
    return r;
}

// ---- Per-pass build kernels (nodeBase = 0 pos / NN neg) ----

__global__ void k_count(const int* __restrict__ row, const int* __restrict__ col,
                        int E, int nodeBase) {
    int e = blockIdx.x * blockDim.x + threadIdx.x;
    if (e >= E) return;
    atomicAdd(&g_cnt[nodeBase + row[e]], 1);
    atomicAdd(&g_cnt[nodeBase + NU + col[e]], 1);
}

__global__ void k_hist(int nodeBase, int bucketBase) {
    __shared__ int sh[NBUCK];
    for (int b = threadIdx.x; b < NBUCK; b += blockDim.x) sh[b] = 0;
    __syncthreads();
    int i = blockIdx.x * blockDim.x + threadIdx.x;
    if (i < NN) atomicAdd(&sh[min(g_cnt[nodeBase + i], NBUCK - 1)], 1);
    __syncthreads();
    for (int b = threadIdx.x; b < NBUCK; b += blockDim.x)
        if (sh[b]) atomicAdd(&g_hist[bucketBase + b], sh[b]);
}

__global__ void k_hscan(int bucketBase) {
    __shared__ int sh[NBUCK];
    int t = threadIdx.x;
    int v = g_hist[bucketBase + t];
    sh[t] = v;
    __syncthreads();
    for (int o = 1; o < NBUCK; o <<= 1) {
        int x = (t >= o) ? sh[t - o] : 0;
        __syncthreads();
        sh[t] += x;
        __syncthreads();
    }
    g_hoff[bucketBase + t] = sh[t] - v;
}

__global__ void k_perm(int nodeBase, int bucketBase) {
    __shared__ int sh_cnt[NBUCK];
    __shared__ int sh_base[NBUCK];
    for (int b = threadIdx.x; b < NBUCK; b += blockDim.x) sh_cnt[b] = 0;
    __syncthreads();
    int i = blockIdx.x * blockDim.x + threadIdx.x;
    int b = -1;
    if (i < NN) {
        b = min(g_cnt[nodeBase + i], NBUCK - 1);
        atomicAdd(&sh_cnt[b], 1);
    }
    __syncthreads();
    for (int bb = threadIdx.x; bb < NBUCK; bb += blockDim.x) {
        int c = sh_cnt[bb];
        sh_base[bb] = c ? atomicAdd(&g_hoff[bucketBase + bb], c) : 0;
        sh_cnt[bb] = 0;
    }
    __syncthreads();
    if (i < NN) {
        int r = atomicAdd(&sh_cnt[b], 1);
        int p = nodeBase + sh_base[b] + r;
        g_perm[p] = nodeBase + i;
        g_rank[nodeBase + i] = p;
    }
}

__global__ void k_scanA(int rankBase, int soffBase, int* __restrict__ bsum) {
    __shared__ int wsum[16];
    int base = blockIdx.x * SCAN_ITEMS + threadIdx.x * 4;
    int v[4]; int s = 0;
#pragma unroll
    for (int j = 0; j < 4; j++) {
        int idx = base + j;
        v[j] = (idx < NN) ? g_cnt[g_perm[rankBase + idx]] : 0;
        s += v[j];
    }
    int lane = threadIdx.x & 31, warp = threadIdx.x >> 5;
    int incl = s;
#pragma unroll
    for (int o = 1; o < 32; o <<= 1) {
        int t = __shfl_up_sync(~0u, incl, o);
        if (lane >= o) incl += t;
    }
    if (lane == 31) wsum[warp] = incl;
    __syncthreads();
    if (warp == 0 && lane < 16) {
        int ws = wsum[lane];
#pragma unroll
        for (int o = 1; o < 16; o <<= 1) {
            int t = __shfl_up_sync(0xffffu, ws, o);
            if (lane >= o) ws += t;
        }
        wsum[lane] = ws;
    }
    __syncthreads();
    int excl = incl - s + (warp ? wsum[warp - 1] : 0);
    int run = excl;
#pragma unroll
    for (int j = 0; j < 4; j++) {
        int idx = base + j;
        if (idx < NN) g_soff[soffBase + idx] = run;
        run += v[j];
    }
    if (threadIdx.x == 0) bsum[blockIdx.x] = wsum[15];
}

__global__ void k_scanB(int* __restrict__ bsum, int nb) {
    __shared__ int sh[MAX_NB];
    int t = threadIdx.x;
    int v = (t < nb) ? bsum[t] : 0;
    sh[t] = v;
    __syncthreads();
    for (int o = 1; o < MAX_NB; o <<= 1) {
        int x = (t >= o) ? sh[t - o] : 0;
        __syncthreads();
        sh[t] += x;
        __syncthreads();
    }
    if (t < nb) bsum[t] = sh[t] - v;
}

__global__ void k_scanC(int rankBase, int soffBase, const int* __restrict__ bsum,
                        int edgeBase, int edgeEnd) {
    int i = blockIdx.x * blockDim.x + threadIdx.x;
    if (i < NN) {
        int o = g_soff[soffBase + i] + bsum[i / SCAN_ITEMS] + edgeBase;
        g_soff[soffBase + i] = o;
        g_cur[g_perm[rankBase + i]] = o;
    }
    if (i == 0) g_soff[soffBase + NN] = edgeEnd;
}

__global__ void k_fill(const int* __restrict__ row, const int* __restrict__ col,
                       const float* __restrict__ w, int E, int nodeBase) {
    int e = blockIdx.x * blockDim.x + threadIdx.x;
    if (e >= E) return;
    int r = row[e], c = col[e];
    float wv = w ? w[e] : 1.f;
    int gu = nodeBase + r, gi = nodeBase + NU + c;
    float nrm = rsqrtf((float)g_cnt[gu]) * rsqrtf((float)g_cnt[gi]) * wv;
    int ru = g_rank[gu], ri = g_rank[gi];
    int p0 = atomicAdd(&g_cur[gu], 1);
    g_pl[p0] = make_float2(__int_as_float(ri), nrm);
    int p1 = atomicAdd(&g_cur[gi], 1);
    g_pl[p1] = make_float2(__int_as_float(ru), nrm);
}

__device__ __forceinline__ const float4* node_emb(
    int node, const float4* up, const float4* ip,
    const float4* un, const float4* in_, int& li_out)
{
    int s = node >= NN;
    int n = s ? node - NN : node;
    const float4* e;
    int li;
    if (n < NU) { li = n;      e = s ? un : up; }
    else        { li = n - NU; e = s ? in_ : ip; }
    li_out = li;
    return e + (size_t)li * 16;
}

__global__ void k_init(const float4* __restrict__ up, const float4* __restrict__ ip,
                       const float4* __restrict__ un, const float4* __restrict__ in_,
                       int rankBase, int soffBase) {
    int gid = blockIdx.x * blockDim.x + threadIdx.x;
    int gl = gid >> 3;
    int t = gid & 7;
    if (gl >= NN) return;
    if (g_soff[soffBase + gl + 1] == g_soff[soffBase + gl]) return;   // deg 0
    int g = rankBase + gl;
    int node = g_perm[g];
    int li;
    const float4* src = node_emb(node, up, ip, un, in_, li);
    float4 a = __ldg(src + t * 2);
    float4 b = __ldg(src + t * 2 + 1);
    g_e[0][g * 8 + t] = pack8(a, b);
}

// Gather layers 1..3: rank space, 8 thr/node, 8/4/1 unroll, FFMA2 math.
__global__ void k_gather(int k, int rankBase, int soffBase) {
    int gid = blockIdx.x * blockDim.x + threadIdx.x;
    int gl = gid >> 3;
    int t = gid & 7;
    if (gl >= NN) return;
    int beg = g_soff[soffBase + gl];
    int cnt = g_soff[soffBase + gl + 1] - beg;
    if (cnt == 0) return;
    int g = rankBase + gl;

    const uint4* __restrict__ src = g_e[k - 1];
    uint4* __restrict__ dst = g_e[k];

    unsigned long long acc[4];
    acc_init(acc, __ldg(src + g * 8 + t));

    const float2* pl = g_pl + beg;
    int j = 0;
    for (; j + 8 <= cnt; j += 8) {
        float2 p[8];
#pragma unroll
        for (int q = 0; q < 8; q++) p[q] = __ldg(pl + j + q);
        uint4 w[8];
#pragma unroll
        for (int q = 0; q < 8; q++)
            w[q] = __ldg(src + __float_as_int(p[q].x) * 8 + t);
#pragma unroll
        for (int q = 0; q < 8; q++)
            fma8p(acc, w[q], packf2(p[q].y, p[q].y));
    }
    if (j + 4 <= cnt) {
        float2 p[4];
#pragma unroll
        for (int q = 0; q < 4; q++) p[q] = __ldg(pl + j + q);
        uint4 w[4];
#pragma unroll
        for (int q = 0; q < 4; q++)
            w[q] = __ldg(src + __float_as_int(p[q].x) * 8 + t);
#pragma unroll
        for (int q = 0; q < 4; q++)
            fma8p(acc, w[q], packf2(p[q].y, p[q].y));
        j += 4;
    }
    for (; j < cnt; j++) {
        float2 p0 = __ldg(pl + j);
        uint4 w0 = __ldg(src + __float_as_int(p0.x) * 8 + t);
        fma8p(acc, w0, packf2(p0.y, p0.y));
    }

    dst[g * 8 + t] = acc_pack16(acc);
}

// Layer 4 fused with output epilogue (FFMA2 path):
// acc = e4; out = (e0 + e1 + e2 + e3 + acc) * inv. Deg-0: out = fp32 emb.
__global__ void k_gather_final(const float4* __restrict__ up, const float4* __restrict__ ip,
                               const float4* __restrict__ un, const float4* __restrict__ in_,
                               float4* __restrict__ out, float inv,
                               int rankBase, int soffBase) {
    int gid = blockIdx.x * blockDim.x + threadIdx.x;
    int gl = gid >> 3;
    int t = gid & 7;
    if (gl >= NN) return;
    int beg = g_soff[soffBase + gl];
    int cnt = g_soff[soffBase + gl + 1] - beg;
    int g = rankBase + gl;
    int node = g_perm[g];

    size_t obase;
    {
        int s = node >= NN;
        int n = s ? node - NN : node;
        int li;
        if (n < NU) { li = n;      obase = (size_t)(s ? (NU + NI) : 0) * 16; }
        else        { li = n - NU; obase = (size_t)(s ? (2 * NU + NI) : NU) * 16; }
        obase += (size_t)li * 16;
    }

    if (cnt == 0) {
        int li;
        const float4* esrc = node_emb(node, up, ip, un, in_, li);
        out[obase + t * 2]     = __ldg(esrc + t * 2);
        out[obase + t * 2 + 1] = __ldg(esrc + t * 2 + 1);
        return;
    }

    const uint4* __restrict__ src = g_e[3];

    unsigned long long acc[4];
    acc_init(acc, __ldg(src + g * 8 + t));   // e3 self term -> becomes e4

    const float2* pl = g_pl + beg;
    int j = 0;
    for (; j + 8 <= cnt; j += 8) {
        float2 p[8];
#pragma unroll
        for (int q = 0; q < 8; q++) p[q] = __ldg(pl + j + q);
        uint4 w[8];
#pragma unroll
        for (int q = 0; q < 8; q++)
            w[q] = __ldg(src + __float_as_int(p[q].x) * 8 + t);
#pragma unroll
        for (int q = 0; q < 8; q++)
            fma8p(acc, w[q], packf2(p[q].y, p[q].y));
    }
    if (j + 4 <= cnt) {
        float2 p[4];
#pragma unroll
        for (int q = 0; q < 4; q++) p[q] = __ldg(pl + j + q);
        uint4 w[4];
#pragma unroll
        for (int q = 0; q < 4; q++)
            w[q] = __ldg(src + __float_as_int(p[q].x) * 8 + t);
#pragma unroll
        for (int q = 0; q < 4; q++)
            fma8p(acc, w[q], packf2(p[q].y, p[q].y));
        j += 4;
    }
    for (; j < cnt; j++) {
        float2 p0 = __ldg(pl + j);
        uint4 w0 = __ldg(src + __float_as_int(p0.x) * 8 + t);
        fma8p(acc, w0, packf2(p0.y, p0.y));
    }

    // epilogue: acc += e0 + e1 + e2 + e3 (packed adds), then * inv
#pragma unroll
    for (int k = 0; k <= 3; k++) {
        uint4 v = __ldg(&g_e[k][g * 8 + t]);
        __half2* hp = (__half2*)&v;
#pragma unroll
        for (int i = 0; i < 4; i++) {
            float2 f = __half22float2(hp[i]);
            fadd2(acc[i], packf2(f.x, f.y));
        }
    }
    float2 r0 = unpackf2(acc[0]);
    float2 r1 = unpackf2(acc[1]);
    float2 r2 = unpackf2(acc[2]);
    float2 r3 = unpackf2(acc[3]);
    out[obase + t * 2]     = make_float4(r0.x * inv, r0.y * inv, r1.x * inv, r1.y * inv);
    out[obase + t * 2 + 1] = make_float4(r2.x * inv, r2.y * inv, r3.x * inv, r3.y * inv);
}

// Restore zero-state invariant for next replay.
__global__ void k_cleanup() {
    int i = blockIdx.x * blockDim.x + threadIdx.x;
    if (i < NN2) g_cnt[i] = 0;
    if (i < 2 * NBUCK) g_hist[i] = 0;
}

extern "C" void kernel_launch(void* const* d_in, const int* in_sizes, int n_in,
                              void* d_out, int out_size) {
    const int*   ei  = (const int*)d_in[0];
    const int*   nei = (const int*)d_in[1];
    const float* ew  = (const float*)d_in[2];
    const float* up  = (const float*)d_in[3];
    const float* ip  = (const float*)d_in[4];
    const float* un  = (const float*)d_in[5];
    const float* inw = (const float*)d_in[6];
    float* out = (float*)d_out;

    const int Epos = in_sizes[0] / 2;
    const int Eneg = in_sizes[1] / 2;
    const float inv = 1.0f / 5.0f;

    const int* prow = ei;
    const int* pcol = ei + Epos;
    const int* nrow = nei;
    const int* ncol = nei + Eneg;

    const int TB = 256;
    const int gNodeH = (NN + TB - 1) / TB;
    const int gNode2 = (NN2 + TB - 1) / TB;
    const int gEp    = (Epos + TB - 1) / TB;
    const int gEn    = (Eneg + TB - 1) / TB;
    const int NBh    = (NN + SCAN_ITEMS - 1) / SCAN_ITEMS;
    const int gW     = (NN * 8 + TB - 1) / TB;

    const int SOFF_P = 0;
    const int SOFF_N = NN + 1;

    static cudaStream_t s2 = nullptr;
    static cudaEvent_t evPF = nullptr, evJoin = nullptr;
    if (!s2) {
        bool ok =
            (cudaStreamCreateWithFlags(&s2, cudaStreamNonBlocking) == cudaSuccess) &&
            (cudaEventCreateWithFlags(&evPF, cudaEventDisableTiming) == cudaSuccess) &&
            (cudaEventCreateWithFlags(&evJoin, cudaEventDisableTiming) == cudaSuccess);
        if (!ok) s2 = nullptr;
    }

    if (s2) {
        // ---- POS pipeline on main stream ----
        k_count<<<gEp, TB>>>(prow, pcol, Epos, 0);
        k_hist<<<gNodeH, TB>>>(0, 0);
        k_hscan<<<1, NBUCK>>>(0);
        k_perm<<<gNodeH, TB>>>(0, 0);
        k_scanA<<<NBh, 512>>>(0, SOFF_P, g_bsumP);
        k_scanB<<<1, MAX_NB>>>(g_bsumP, NBh);
        k_scanC<<<gNodeH, TB>>>(0, SOFF_P, g_bsumP, 0, 2 * Epos);
        k_fill<<<gEp, TB>>>(prow, pcol, ew, Epos, 0);
        cudaEventRecord(evPF, 0);
        k_init<<<gW, TB>>>((const float4*)up, (const float4*)ip,
                           (const float4*)un, (const float4*)inw, 0, SOFF_P);

        // ---- NEG pipeline on s2 (fully disjoint arrays/slots) ----
        k_count<<<gEn, TB, 0, s2>>>(nrow, ncol, Eneg, NN);
        k_hist<<<gNodeH, TB, 0, s2>>>(NN, NBUCK);
        k_hscan<<<1, NBUCK, 0, s2>>>(NBUCK);
        k_perm<<<gNodeH, TB, 0, s2>>>(NN, NBUCK);
        k_scanA<<<NBh, 512, 0, s2>>>(NN, SOFF_N, g_bsumN);
        k_scanB<<<1, MAX_NB, 0, s2>>>(g_bsumN, NBh);
        k_scanC<<<gNodeH, TB, 0, s2>>>(NN, SOFF_N, g_bsumN, 2 * Epos, 2 * (Epos + Eneg));
        k_fill<<<gEn, TB, 0, s2>>>(nrow, ncol, nullptr, Eneg, NN);
        k_init<<<gW, TB, 0, s2>>>((const float4*)up, (const float4*)ip,
                                  (const float4*)un, (const float4*)inw, NN, SOFF_N);
        cudaStreamWaitEvent(s2, evPF, 0);
        k_cleanup<<<gNode2, TB, 0, s2>>>();

        for (int l = 1; l <= 3; l++)
            k_gather<<<gW, TB, 0, s2>>>(l, NN, SOFF_N);
        k_gather_final<<<gW, TB, 0, s2>>>((const float4*)up, (const float4*)ip,
                                          (const float4*)un, (const float4*)inw,
                                          (float4*)out, inv, NN, SOFF_N);
        cudaEventRecord(evJoin, s2);

        // ---- POS gathers on main ----
        for (int l = 1; l <= 3; l++)
            k_gather<<<gW, TB>>>(l, 0, SOFF_P);
        k_gather_final<<<gW, TB>>>((const float4*)up, (const float4*)ip,
                                   (const float4*)un, (const float4*)inw,
                                   (float4*)out, inv, 0, SOFF_P);

        cudaStreamWaitEvent(0, evJoin, 0);
    } else {
        // Serial fallback
        k_count<<<gEp, TB>>>(prow, pcol, Epos, 0);
        k_count<<<gEn, TB>>>(nrow, ncol, Eneg, NN);
        k_hist<<<gNodeH, TB>>>(0, 0);
        k_hist<<<gNodeH, TB>>>(NN, NBUCK);
        k_hscan<<<1, NBUCK>>>(0);
        k_hscan<<<1, NBUCK>>>(NBUCK);
        k_perm<<<gNodeH, TB>>>(0, 0);
        k_perm<<<gNodeH, TB>>>(NN, NBUCK);
        k_scanA<<<NBh, 512>>>(0, SOFF_P, g_bsumP);
        k_scanA<<<NBh, 512>>>(NN, SOFF_N, g_bsumN);
        k_scanB<<<1, MAX_NB>>>(g_bsumP, NBh);
        k_scanB<<<1, MAX_NB>>>(g_bsumN, NBh);
        k_scanC<<<gNodeH, TB>>>(0, SOFF_P, g_bsumP, 0, 2 * Epos);
        k_scanC<<<gNodeH, TB>>>(NN, SOFF_N, g_bsumN, 2 * Epos, 2 * (Epos + Eneg));
        k_fill<<<gEp, TB>>>(prow, pcol, ew, Epos, 0);
        k_fill<<<gEn, TB>>>(nrow, ncol, nullptr, Eneg, NN);
        k_init<<<gW, TB>>>((const float4*)up, (const float4*)ip,
                           (const float4*)un, (const float4*)inw, 0, SOFF_P);
        k_init<<<gW, TB>>>((const float4*)up, (const float4*)ip,
                           (const float4*)un, (const float4*)inw, NN, SOFF_N);
        for (int s = 0; s < 2; s++) {
            int rb = s * NN, sb = s ? SOFF_N : SOFF_P;
            for (int l = 1; l <= 3; l++)
                k_gather<<<gW, TB>>>(l, rb, sb);
            k_gather_final<<<gW, TB>>>((const float4*)up, (const float4*)ip,
                                       (const float4*)un, (const float4*)inw,
                                       (float4*)out, inv, rb, sb);
        }
        k_cleanup<<<gNode2, TB>>>();
    }
}